// round 4
// baseline (speedup 1.0000x reference)
#include <cuda_runtime.h>

#define NEG_SLOPE 0.04821699482733621f
#define MAXN 50000
#define HC 128

// ---------------- device scratch (no allocations allowed) ----------------
__device__ __align__(16) float g_h[(size_t)MAXN * HC];     // 25.6 MB
__device__ __align__(16) float g_as[MAXN * 4];
__device__ __align__(16) float g_ad[MAXN * 4];
__device__ __align__(16) float g_denom[MAXN * 4];
__device__ double g_sum[HC];
__device__ double g_sumsq[HC];
__device__ float  g_mu[HC];
__device__ float  g_inv[HC];

__device__ __forceinline__ void red_add_v4(float* p, float4 v) {
    asm volatile("red.global.add.v4.f32 [%0], {%1,%2,%3,%4};"
                 :: "l"(p), "f"(v.x), "f"(v.y), "f"(v.z), "f"(v.w) : "memory");
}
__device__ __forceinline__ void red_add_f(float* p, float v) {
    asm volatile("red.global.add.f32 [%0], %1;" :: "l"(p), "f"(v) : "memory");
}

// ---------------- 1. GEMM: h = x @ W  (M=N nodes, K=128, N=128) ----------------
__global__ void gemm_kernel(const float* __restrict__ x, const float* __restrict__ W, int N) {
    __shared__ float xs[64][36];    // 64x32 tile, padded stride (16B-aligned rows)
    __shared__ float ws[32][132];   // 32x128 tile, padded stride (16B-aligned rows)
    int tid = threadIdx.x;
    int tx = tid & 15, ty = tid >> 4;
    int row0 = blockIdx.x * 64;

    float acc[4][8];
#pragma unroll
    for (int i = 0; i < 4; i++)
#pragma unroll
        for (int j = 0; j < 8; j++) acc[i][j] = 0.f;

    for (int kk = 0; kk < 128; kk += 32) {
        // load x tile: 64 rows x 32 cols = 512 float4
#pragma unroll
        for (int i = 0; i < 2; i++) {
            int f = tid + i * 256;
            int r = f >> 3, q = f & 7;
            float4 v = make_float4(0.f, 0.f, 0.f, 0.f);
            if (row0 + r < N)
                v = *(const float4*)&x[(size_t)(row0 + r) * 128 + kk + q * 4];
            *(float4*)&xs[r][q * 4] = v;
        }
        // load W tile: 32 rows x 128 cols = 1024 float4
#pragma unroll
        for (int i = 0; i < 4; i++) {
            int f = tid + i * 256;
            int r = f >> 5, q = f & 31;
            *(float4*)&ws[r][q * 4] = *(const float4*)&W[(size_t)(kk + r) * 128 + q * 4];
        }
        __syncthreads();
#pragma unroll
        for (int k = 0; k < 32; k++) {
            float a[4];
#pragma unroll
            for (int i = 0; i < 4; i++) a[i] = xs[ty * 4 + i][k];
            float4 b0 = *(float4*)&ws[k][tx * 8];
            float4 b1 = *(float4*)&ws[k][tx * 8 + 4];
            float b[8] = {b0.x, b0.y, b0.z, b0.w, b1.x, b1.y, b1.z, b1.w};
#pragma unroll
            for (int i = 0; i < 4; i++)
#pragma unroll
                for (int j = 0; j < 8; j++) acc[i][j] = fmaf(a[i], b[j], acc[i][j]);
        }
        __syncthreads();
    }
#pragma unroll
    for (int i = 0; i < 4; i++) {
        int r = row0 + ty * 4 + i;
        if (r < N) {
            *(float4*)&g_h[(size_t)r * 128 + tx * 8] =
                make_float4(acc[i][0], acc[i][1], acc[i][2], acc[i][3]);
            *(float4*)&g_h[(size_t)r * 128 + tx * 8 + 4] =
                make_float4(acc[i][4], acc[i][5], acc[i][6], acc[i][7]);
        }
    }
}

// ---------------- 2. per-node attention logits (warp per node) ----------------
__global__ void alpha_kernel(const float* __restrict__ a_src,
                             const float* __restrict__ a_dst, int N) {
    int gw = (blockIdx.x * blockDim.x + threadIdx.x) >> 5;
    int lane = threadIdx.x & 31;
    if (gw >= N) return;
    const float* hr = &g_h[(size_t)gw * 128];
    float v0 = hr[lane], v1 = hr[32 + lane], v2 = hr[64 + lane], v3 = hr[96 + lane];
    float s0 = v0 * a_src[lane],      s1 = v1 * a_src[32 + lane];
    float s2 = v2 * a_src[64 + lane], s3 = v3 * a_src[96 + lane];
    float d0 = v0 * a_dst[lane],      d1 = v1 * a_dst[32 + lane];
    float d2 = v2 * a_dst[64 + lane], d3 = v3 * a_dst[96 + lane];
#pragma unroll
    for (int off = 16; off; off >>= 1) {
        s0 += __shfl_xor_sync(0xffffffffu, s0, off);
        s1 += __shfl_xor_sync(0xffffffffu, s1, off);
        s2 += __shfl_xor_sync(0xffffffffu, s2, off);
        s3 += __shfl_xor_sync(0xffffffffu, s3, off);
        d0 += __shfl_xor_sync(0xffffffffu, d0, off);
        d1 += __shfl_xor_sync(0xffffffffu, d1, off);
        d2 += __shfl_xor_sync(0xffffffffu, d2, off);
        d3 += __shfl_xor_sync(0xffffffffu, d3, off);
    }
    if (lane == 0) {
        *(float4*)&g_as[gw * 4] = make_float4(s0, s1, s2, s3);
        *(float4*)&g_ad[gw * 4] = make_float4(d0, d1, d2, d3);
    }
}

// ---------------- 3. self-loop init: out = h*w_self, denom = w_self ----------------
__global__ void init_kernel(float* __restrict__ out, int N) {
    int idx = blockIdx.x * blockDim.x + threadIdx.x;
    if (idx < HC) { g_sum[idx] = 0.0; g_sumsq[idx] = 0.0; }
    int n = idx >> 5, q = idx & 31;
    if (n >= N) return;
    int head = q >> 3;
    float e = g_as[n * 4 + head] + g_ad[n * 4 + head];
    e = e >= 0.f ? e : NEG_SLOPE * e;
    float w = __expf(e);
    float4 hv = *(const float4*)&g_h[(size_t)n * 128 + q * 4];
    *(float4*)&out[(size_t)n * 128 + q * 4] =
        make_float4(hv.x * w, hv.y * w, hv.z * w, hv.w * w);
    if ((q & 7) == 0) g_denom[n * 4 + head] = w;
}

// ---------------- 4. fused edge pass: denom += exp(e), out[dst] += exp(e)*h[src] ----
__global__ void agg_kernel(const int* __restrict__ src_idx,
                           const int* __restrict__ dst_idx,
                           float* __restrict__ out, int E) {
    int w = blockIdx.x * (blockDim.x >> 5) + (threadIdx.x >> 5);
    if (w >= E) return;
    int lane = threadIdx.x & 31;
    int src = src_idx[w];
    int dst = dst_idx[w];
    int head = lane >> 3;
    float e = g_as[src * 4 + head] + g_ad[dst * 4 + head];
    e = e >= 0.f ? e : NEG_SLOPE * e;
    float wt = __expf(e);
    if ((lane & 7) == 0) red_add_f(&g_denom[dst * 4 + head], wt);
    float4 hv = *(const float4*)&g_h[(size_t)src * 128 + lane * 4];
    red_add_v4(&out[(size_t)dst * 128 + lane * 4],
               make_float4(hv.x * wt, hv.y * wt, hv.z * wt, hv.w * wt));
}

// ---------------- 5. normalize by denom, add bias, accumulate BN stats ----------------
__global__ void stats_kernel(float* __restrict__ out, const float* __restrict__ bias, int N) {
    __shared__ double sh_s[256][4];
    __shared__ double sh_q[256][4];
    int tid = threadIdx.x;
    int q = tid & 31, rg = tid >> 5;
    int head = q >> 3;
    float4 b4 = *(const float4*)&bias[q * 4];
    double s[4] = {0, 0, 0, 0}, ss[4] = {0, 0, 0, 0};
    for (int r = blockIdx.x * 8 + rg; r < N; r += 2048) {
        float4 t = *(float4*)&out[(size_t)r * 128 + q * 4];
        float inv = 1.0f / g_denom[r * 4 + head];
        t.x = t.x * inv + b4.x;
        t.y = t.y * inv + b4.y;
        t.z = t.z * inv + b4.z;
        t.w = t.w * inv + b4.w;
        *(float4*)&out[(size_t)r * 128 + q * 4] = t;
        s[0] += t.x; s[1] += t.y; s[2] += t.z; s[3] += t.w;
        ss[0] += (double)t.x * t.x; ss[1] += (double)t.y * t.y;
        ss[2] += (double)t.z * t.z; ss[3] += (double)t.w * t.w;
    }
#pragma unroll
    for (int j = 0; j < 4; j++) { sh_s[tid][j] = s[j]; sh_q[tid][j] = ss[j]; }
    __syncthreads();
    if (tid < 32) {
        double a[4] = {0, 0, 0, 0}, b[4] = {0, 0, 0, 0};
#pragma unroll
        for (int g = 0; g < 8; g++)
#pragma unroll
            for (int j = 0; j < 4; j++) {
                a[j] += sh_s[g * 32 + tid][j];
                b[j] += sh_q[g * 32 + tid][j];
            }
#pragma unroll
        for (int j = 0; j < 4; j++) {
            atomicAdd(&g_sum[tid * 4 + j], a[j]);
            atomicAdd(&g_sumsq[tid * 4 + j], b[j]);
        }
    }
}

// ---------------- 6. finalize per-channel mean / inv-std ----------------
__global__ void finalize_kernel(const float* __restrict__ gamma, int N) {
    int c = threadIdx.x;
    double mu = g_sum[c] / (double)N;
    double var = g_sumsq[c] / (double)N - mu * mu;
    g_mu[c] = (float)mu;
    g_inv[c] = rsqrtf((float)var + 1e-5f) * gamma[c];
}

// ---------------- 7. apply batchnorm ----------------
__global__ void norm_kernel(float* __restrict__ out, const float* __restrict__ beta, int N) {
    int idx = blockIdx.x * blockDim.x + threadIdx.x;
    int n = idx >> 5, q = idx & 31;
    if (n >= N) return;
    float4 t = *(float4*)&out[(size_t)n * 128 + q * 4];
    float4 mu = *(const float4*)&g_mu[q * 4];
    float4 iv = *(const float4*)&g_inv[q * 4];
    float4 be = *(const float4*)&beta[q * 4];
    t.x = (t.x - mu.x) * iv.x + be.x;
    t.y = (t.y - mu.y) * iv.y + be.y;
    t.z = (t.z - mu.z) * iv.z + be.z;
    t.w = (t.w - mu.w) * iv.w + be.w;
    *(float4*)&out[(size_t)n * 128 + q * 4] = t;
}

// ---------------- launcher ----------------
extern "C" void kernel_launch(void* const* d_in, const int* in_sizes, int n_in,
                              void* d_out, int out_size) {
    const float* x      = (const float*)d_in[0];
    const int*   ei     = (const int*)d_in[1];   // int32: JAX x64 disabled
    const float* W      = (const float*)d_in[2];
    const float* a_src  = (const float*)d_in[3];
    const float* a_dst  = (const float*)d_in[4];
    const float* bias   = (const float*)d_in[5];
    const float* gamma  = (const float*)d_in[6];
    const float* beta   = (const float*)d_in[7];
    float* out = (float*)d_out;

    int N = in_sizes[0] / 128;
    int E = in_sizes[1] / 2;

    gemm_kernel<<<(N + 63) / 64, 256>>>(x, W, N);
    alpha_kernel<<<(N * 32 + 255) / 256, 256>>>(a_src, a_dst, N);
    init_kernel<<<(N * 32 + 255) / 256, 256>>>(out, N);
    agg_kernel<<<(E + 7) / 8, 256>>>(ei, ei + E, out, E);
    stats_kernel<<<256, 256>>>(out, bias, N);
    finalize_kernel<<<1, 128>>>(gamma, N);
    norm_kernel<<<(N * 32 + 255) / 256, 256>>>(out, beta, N);
}

// round 5
// speedup vs baseline: 1.0414x; 1.0414x over previous
#include <cuda_runtime.h>

#define NEG_SLOPE 0.04821699482733621f
#define MAXN 50000
#define MAXE 1600000
#define HC 128

// ---------------- device scratch (no allocations allowed) ----------------
__device__ __align__(16) float g_h[(size_t)MAXN * HC];       // 25.6 MB
__device__ __align__(16) float g_as[MAXN * 4];
__device__ __align__(16) float g_ad[MAXN * 4];
__device__ int   g_cnt[MAXN];
__device__ int   g_cursor[MAXN];
__device__ int   g_row_ptr[MAXN + 1];
__device__ int   g_src_sorted[MAXE];
__device__ __align__(16) float g_wt[(size_t)MAXE * 4];       // 25.6 MB per-edge 4-head weights
__device__ double g_sum[HC];
__device__ double g_sumsq[HC];
__device__ float  g_mu[HC];
__device__ float  g_inv[HC];

__device__ __forceinline__ float leaky_exp(float e) {
    e = e >= 0.f ? e : NEG_SLOPE * e;
    return __expf(e);
}

// ---------------- 1. GEMM: h = x @ W  (M=N nodes, K=128, N=128) ----------------
__global__ void gemm_kernel(const float* __restrict__ x, const float* __restrict__ W, int N) {
    __shared__ float xs[64][36];
    __shared__ float ws[32][132];
    int tid = threadIdx.x;
    int tx = tid & 15, ty = tid >> 4;
    int row0 = blockIdx.x * 64;

    float acc[4][8];
#pragma unroll
    for (int i = 0; i < 4; i++)
#pragma unroll
        for (int j = 0; j < 8; j++) acc[i][j] = 0.f;

    for (int kk = 0; kk < 128; kk += 32) {
#pragma unroll
        for (int i = 0; i < 2; i++) {
            int f = tid + i * 256;
            int r = f >> 3, q = f & 7;
            float4 v = make_float4(0.f, 0.f, 0.f, 0.f);
            if (row0 + r < N)
                v = *(const float4*)&x[(size_t)(row0 + r) * 128 + kk + q * 4];
            *(float4*)&xs[r][q * 4] = v;
        }
#pragma unroll
        for (int i = 0; i < 4; i++) {
            int f = tid + i * 256;
            int r = f >> 5, q = f & 31;
            *(float4*)&ws[r][q * 4] = *(const float4*)&W[(size_t)(kk + r) * 128 + q * 4];
        }
        __syncthreads();
#pragma unroll
        for (int k = 0; k < 32; k++) {
            float a[4];
#pragma unroll
            for (int i = 0; i < 4; i++) a[i] = xs[ty * 4 + i][k];
            float4 b0 = *(float4*)&ws[k][tx * 8];
            float4 b1 = *(float4*)&ws[k][tx * 8 + 4];
            float b[8] = {b0.x, b0.y, b0.z, b0.w, b1.x, b1.y, b1.z, b1.w};
#pragma unroll
            for (int i = 0; i < 4; i++)
#pragma unroll
                for (int j = 0; j < 8; j++) acc[i][j] = fmaf(a[i], b[j], acc[i][j]);
        }
        __syncthreads();
    }
#pragma unroll
    for (int i = 0; i < 4; i++) {
        int r = row0 + ty * 4 + i;
        if (r < N) {
            *(float4*)&g_h[(size_t)r * 128 + tx * 8] =
                make_float4(acc[i][0], acc[i][1], acc[i][2], acc[i][3]);
            *(float4*)&g_h[(size_t)r * 128 + tx * 8 + 4] =
                make_float4(acc[i][4], acc[i][5], acc[i][6], acc[i][7]);
        }
    }
}

// ---------------- 2. per-node attention logits (warp per node) ----------------
__global__ void alpha_kernel(const float* __restrict__ a_src,
                             const float* __restrict__ a_dst, int N) {
    int gw = (blockIdx.x * blockDim.x + threadIdx.x) >> 5;
    int lane = threadIdx.x & 31;
    if (gw >= N) return;
    const float* hr = &g_h[(size_t)gw * 128];
    float v0 = hr[lane], v1 = hr[32 + lane], v2 = hr[64 + lane], v3 = hr[96 + lane];
    float s0 = v0 * a_src[lane],      s1 = v1 * a_src[32 + lane];
    float s2 = v2 * a_src[64 + lane], s3 = v3 * a_src[96 + lane];
    float d0 = v0 * a_dst[lane],      d1 = v1 * a_dst[32 + lane];
    float d2 = v2 * a_dst[64 + lane], d3 = v3 * a_dst[96 + lane];
#pragma unroll
    for (int off = 16; off; off >>= 1) {
        s0 += __shfl_xor_sync(0xffffffffu, s0, off);
        s1 += __shfl_xor_sync(0xffffffffu, s1, off);
        s2 += __shfl_xor_sync(0xffffffffu, s2, off);
        s3 += __shfl_xor_sync(0xffffffffu, s3, off);
        d0 += __shfl_xor_sync(0xffffffffu, d0, off);
        d1 += __shfl_xor_sync(0xffffffffu, d1, off);
        d2 += __shfl_xor_sync(0xffffffffu, d2, off);
        d3 += __shfl_xor_sync(0xffffffffu, d3, off);
    }
    if (lane == 0) {
        *(float4*)&g_as[gw * 4] = make_float4(s0, s1, s2, s3);
        *(float4*)&g_ad[gw * 4] = make_float4(d0, d1, d2, d3);
    }
}

// ---------------- 3. zero counters + BN accumulators ----------------
__global__ void zero_kernel(int N) {
    int idx = blockIdx.x * blockDim.x + threadIdx.x;
    if (idx < HC) { g_sum[idx] = 0.0; g_sumsq[idx] = 0.0; }
    if (idx < N) g_cnt[idx] = 0;
}

// ---------------- 4. histogram of destination degrees ----------------
__global__ void hist_kernel(const int* __restrict__ dst_idx, int E) {
    int e = blockIdx.x * blockDim.x + threadIdx.x;
    if (e < E) atomicAdd(&g_cnt[dst_idx[e]], 1);
}

// ---------------- 5. exclusive prefix scan (single block) ----------------
__global__ void scan_kernel(int N, int E) {
    __shared__ int sh[32];
    int t = threadIdx.x;
    int chunk = (N + 1023) / 1024;
    int start = t * chunk;
    int end = min(start + chunk, N);
    int sum = 0;
    for (int i = start; i < end; i++) sum += g_cnt[i];
    int lane = t & 31, wid = t >> 5;
    int inc = sum;
#pragma unroll
    for (int off = 1; off < 32; off <<= 1) {
        int v = __shfl_up_sync(0xffffffffu, inc, off);
        if (lane >= off) inc += v;
    }
    if (lane == 31) sh[wid] = inc;
    __syncthreads();
    if (wid == 0) {
        int v = sh[lane];
#pragma unroll
        for (int off = 1; off < 32; off <<= 1) {
            int u = __shfl_up_sync(0xffffffffu, v, off);
            if (lane >= off) v += u;
        }
        sh[lane] = v;
    }
    __syncthreads();
    int base = (wid > 0) ? sh[wid - 1] : 0;
    int run = base + inc - sum;          // exclusive prefix for this thread's range
    for (int i = start; i < end; i++) {
        g_row_ptr[i] = run;
        g_cursor[i] = run;
        run += g_cnt[i];
    }
    if (t == 0) g_row_ptr[N] = E;
}

// ---------------- 6. scatter edges into CSR + precompute 4-head weights ------
__global__ void scatter_kernel(const int* __restrict__ src_idx,
                               const int* __restrict__ dst_idx, int E) {
    int e = blockIdx.x * blockDim.x + threadIdx.x;
    if (e >= E) return;
    int src = src_idx[e];
    int dst = dst_idx[e];
    float4 as4 = *(const float4*)&g_as[src * 4];
    float4 ad4 = *(const float4*)&g_ad[dst * 4];
    float4 w;
    w.x = leaky_exp(as4.x + ad4.x);
    w.y = leaky_exp(as4.y + ad4.y);
    w.z = leaky_exp(as4.z + ad4.z);
    w.w = leaky_exp(as4.w + ad4.w);
    int pos = atomicAdd(&g_cursor[dst], 1);
    g_src_sorted[pos] = src;
    *(float4*)&g_wt[(size_t)pos * 4] = w;
}

// ---------------- 7. warp-per-dst aggregation (no atomics) --------------------
__global__ void agg2_kernel(float* __restrict__ out,
                            const float* __restrict__ bias, int N) {
    int n = blockIdx.x * (blockDim.x >> 5) + (threadIdx.x >> 5);
    if (n >= N) return;
    int lane = threadIdx.x & 31;
    int head = lane >> 3;

    // self-loop contribution
    float e0 = g_as[n * 4 + head] + g_ad[n * 4 + head];
    float w0 = leaky_exp(e0);
    float4 hv = *(const float4*)&g_h[(size_t)n * 128 + lane * 4];
    float4 acc = make_float4(w0 * hv.x, w0 * hv.y, w0 * hv.z, w0 * hv.w);
    float dsum = w0;

    int s = g_row_ptr[n];
    int e = g_row_ptr[n + 1];
    for (int base = s; base < e; base += 32) {
        int k = base + lane;
        int src_l = (k < e) ? g_src_sorted[k] : 0;
        int m = min(32, e - base);
#pragma unroll 4
        for (int j = 0; j < m; j++) {
            int src = __shfl_sync(0xffffffffu, src_l, j);
            float wj = g_wt[(size_t)(base + j) * 4 + head];
            float4 hj = *(const float4*)&g_h[(size_t)src * 128 + lane * 4];
            acc.x = fmaf(wj, hj.x, acc.x);
            acc.y = fmaf(wj, hj.y, acc.y);
            acc.z = fmaf(wj, hj.z, acc.z);
            acc.w = fmaf(wj, hj.w, acc.w);
            dsum += wj;
        }
    }
    float inv = 1.0f / dsum;
    float4 b4 = *(const float4*)&bias[lane * 4];
    float4 t;
    t.x = fmaf(acc.x, inv, b4.x);
    t.y = fmaf(acc.y, inv, b4.y);
    t.z = fmaf(acc.z, inv, b4.z);
    t.w = fmaf(acc.w, inv, b4.w);
    *(float4*)&out[(size_t)n * 128 + lane * 4] = t;
}

// ---------------- 8. BN stats (read-only pass over out) ----------------
__global__ void stats_kernel(const float* __restrict__ out, int N) {
    __shared__ double sh_s[256][4];
    __shared__ double sh_q[256][4];
    int tid = threadIdx.x;
    int q = tid & 31, rg = tid >> 5;
    double s[4] = {0, 0, 0, 0}, ss[4] = {0, 0, 0, 0};
    for (int r = blockIdx.x * 8 + rg; r < N; r += 2048) {
        float4 t = *(const float4*)&out[(size_t)r * 128 + q * 4];
        s[0] += t.x; s[1] += t.y; s[2] += t.z; s[3] += t.w;
        ss[0] += (double)t.x * t.x; ss[1] += (double)t.y * t.y;
        ss[2] += (double)t.z * t.z; ss[3] += (double)t.w * t.w;
    }
#pragma unroll
    for (int j = 0; j < 4; j++) { sh_s[tid][j] = s[j]; sh_q[tid][j] = ss[j]; }
    __syncthreads();
    if (tid < 32) {
        double a[4] = {0, 0, 0, 0}, b[4] = {0, 0, 0, 0};
#pragma unroll
        for (int g = 0; g < 8; g++)
#pragma unroll
            for (int j = 0; j < 4; j++) {
                a[j] += sh_s[g * 32 + tid][j];
                b[j] += sh_q[g * 32 + tid][j];
            }
#pragma unroll
        for (int j = 0; j < 4; j++) {
            atomicAdd(&g_sum[tid * 4 + j], a[j]);
            atomicAdd(&g_sumsq[tid * 4 + j], b[j]);
        }
    }
}

// ---------------- 9. finalize per-channel mean / inv-std ----------------
__global__ void finalize_kernel(const float* __restrict__ gamma, int N) {
    int c = threadIdx.x;
    double mu = g_sum[c] / (double)N;
    double var = g_sumsq[c] / (double)N - mu * mu;
    g_mu[c] = (float)mu;
    g_inv[c] = rsqrtf((float)var + 1e-5f) * gamma[c];
}

// ---------------- 10. apply batchnorm ----------------
__global__ void norm_kernel(float* __restrict__ out, const float* __restrict__ beta, int N) {
    int idx = blockIdx.x * blockDim.x + threadIdx.x;
    int n = idx >> 5, q = idx & 31;
    if (n >= N) return;
    float4 t = *(float4*)&out[(size_t)n * 128 + q * 4];
    float4 mu = *(const float4*)&g_mu[q * 4];
    float4 iv = *(const float4*)&g_inv[q * 4];
    float4 be = *(const float4*)&beta[q * 4];
    t.x = (t.x - mu.x) * iv.x + be.x;
    t.y = (t.y - mu.y) * iv.y + be.y;
    t.z = (t.z - mu.z) * iv.z + be.z;
    t.w = (t.w - mu.w) * iv.w + be.w;
    *(float4*)&out[(size_t)n * 128 + q * 4] = t;
}

// ---------------- launcher ----------------
extern "C" void kernel_launch(void* const* d_in, const int* in_sizes, int n_in,
                              void* d_out, int out_size) {
    const float* x      = (const float*)d_in[0];
    const int*   ei     = (const int*)d_in[1];   // int32: JAX x64 disabled
    const float* W      = (const float*)d_in[2];
    const float* a_src  = (const float*)d_in[3];
    const float* a_dst  = (const float*)d_in[4];
    const float* bias   = (const float*)d_in[5];
    const float* gamma  = (const float*)d_in[6];
    const float* beta   = (const float*)d_in[7];
    float* out = (float*)d_out;

    int N = in_sizes[0] / 128;
    int E = in_sizes[1] / 2;
    const int* src_idx = ei;
    const int* dst_idx = ei + E;

    gemm_kernel<<<(N + 63) / 64, 256>>>(x, W, N);
    alpha_kernel<<<(N * 32 + 255) / 256, 256>>>(a_src, a_dst, N);
    zero_kernel<<<(N + 255) / 256, 256>>>(N);
    hist_kernel<<<(E + 255) / 256, 256>>>(dst_idx, E);
    scan_kernel<<<1, 1024>>>(N, E);
    scatter_kernel<<<(E + 255) / 256, 256>>>(src_idx, dst_idx, E);
    agg2_kernel<<<(N + 7) / 8, 256>>>(out, bias, N);
    stats_kernel<<<256, 256>>>(out, N);
    finalize_kernel<<<1, 128>>>(gamma, N);
    norm_kernel<<<(N * 32 + 255) / 256, 256>>>(out, beta, N);
}